// round 7
// baseline (speedup 1.0000x reference)
#include <cuda_runtime.h>
#include <math.h>

#define NMAX 100000
#define EMAX 1600000
#define D 64
#define KDIM 192
#define OUTC 64

typedef unsigned long long u64;

// ---- scratch ----
__device__ int g_cnt[NMAX];
__device__ int g_start[NMAX + 1];
__device__ int g_cursor[NMAX];
__device__ int g_adj[EMAX];
__device__ int g_bsum[260];
__device__ int g_total;

// ---------------- CSR build ----------------

__global__ void zero_cnt_kernel(int n) {
    int i = blockIdx.x * blockDim.x + threadIdx.x;
    if (i < n) g_cnt[i] = 0;
}

__global__ void hist_kernel(const int* __restrict__ row, int E) {
    int i = blockIdx.x * blockDim.x + threadIdx.x;
    if (i < E) atomicAdd(&g_cnt[row[i]], 1);
}

#define SCAN_B 512

__global__ __launch_bounds__(SCAN_B) void scan_partial_kernel(int n) {
    __shared__ int ws[16];
    int blk = blockIdx.x, tid = threadIdx.x;
    int i = blk * SCAN_B + tid;
    int v = (i < n) ? g_cnt[i] : 0;
    int lane = tid & 31, wid = tid >> 5;
    int x = v;
    #pragma unroll
    for (int o = 1; o < 32; o <<= 1) {
        int y = __shfl_up_sync(0xffffffffu, x, o);
        if (lane >= o) x += y;
    }
    if (lane == 31) ws[wid] = x;
    __syncthreads();
    if (wid == 0 && lane < 16) {
        int w = ws[lane];
        #pragma unroll
        for (int o = 1; o < 16; o <<= 1) {
            int y = __shfl_up_sync(0x0000ffffu, w, o);
            if (lane >= o) w += y;
        }
        ws[lane] = w;
    }
    __syncthreads();
    int incl = x + (wid > 0 ? ws[wid - 1] : 0);
    if (i < n) g_start[i] = incl - v;
    if (tid == SCAN_B - 1) g_bsum[blk] = incl;
}

__global__ __launch_bounds__(256) void scan_bsums_kernel(int nb) {
    __shared__ int ws[8];
    int tid = threadIdx.x;
    int v = (tid < nb) ? g_bsum[tid] : 0;
    int lane = tid & 31, wid = tid >> 5;
    int x = v;
    #pragma unroll
    for (int o = 1; o < 32; o <<= 1) {
        int y = __shfl_up_sync(0xffffffffu, x, o);
        if (lane >= o) x += y;
    }
    if (lane == 31) ws[wid] = x;
    __syncthreads();
    if (wid == 0 && lane < 8) {
        int w = ws[lane];
        #pragma unroll
        for (int o = 1; o < 8; o <<= 1) {
            int y = __shfl_up_sync(0x000000ffu, w, o);
            if (lane >= o) w += y;
        }
        ws[lane] = w;
    }
    __syncthreads();
    int incl = x + (wid > 0 ? ws[wid - 1] : 0);
    g_bsum[tid] = incl - v;
    if (tid == 255) g_total = incl;
}

__global__ __launch_bounds__(SCAN_B) void scan_add_kernel(int n) {
    int i = blockIdx.x * SCAN_B + threadIdx.x;
    if (i < n) {
        int s = g_start[i] + g_bsum[blockIdx.x];
        g_start[i] = s;
        g_cursor[i] = s;
    }
    if (i == 0) g_start[n] = g_total;
}

__global__ void scatter_kernel(const int* __restrict__ row,
                               const int* __restrict__ col, int E) {
    int i = blockIdx.x * blockDim.x + threadIdx.x;
    if (i < E) {
        int p = atomicAdd(&g_cursor[row[i]], 1);
        g_adj[p] = col[i];
    }
}

// ---------------- fused aggregate + MLP ----------------
// Phase 1: 16 half-warps aggregate 64 nodes (4 each) into k-major smem As[192][66].
// Phase 2: FFMA2 GEMM As x Ws (W cached in smem) + bias + tanh -> out.

#define FM 64
#define SA 66                       // As row stride (floats): 8B-aligned LDS.64
#define SMEM_FLOATS (KDIM * SA + KDIM * OUTC)
#define SMEM_BYTES  (SMEM_FLOATS * 4)

__device__ __forceinline__ void facc4(float4& sm, float4& mx, float4& mn, float4 f) {
    sm.x += f.x;  sm.y += f.y;  sm.z += f.z;  sm.w += f.w;
    mx.x = fmaxf(mx.x, f.x);  mx.y = fmaxf(mx.y, f.y);
    mx.z = fmaxf(mx.z, f.z);  mx.w = fmaxf(mx.w, f.w);
    mn.x = fminf(mn.x, f.x);  mn.y = fminf(mn.y, f.y);
    mn.z = fminf(mn.z, f.z);  mn.w = fminf(mn.w, f.w);
}

__device__ __forceinline__ u64 pack2(float lo, float hi) {
    u64 r; asm("mov.b64 %0, {%1, %2};" : "=l"(r) : "f"(lo), "f"(hi)); return r;
}
__device__ __forceinline__ void ffma2(u64& d, u64 a, u64 b) {
    asm("fma.rn.f32x2 %0, %1, %2, %0;" : "+l"(d) : "l"(a), "l"(b));
}
__device__ __forceinline__ float2 unpack2(u64 v) {
    float2 f; asm("mov.b64 {%0, %1}, %2;" : "=f"(f.x), "=f"(f.y) : "l"(v)); return f;
}

__global__ __launch_bounds__(256) void fused_kernel(
    const float* __restrict__ feat,
    const float* __restrict__ Wg,     // [192,64] row(k)-major
    const float* __restrict__ bg,     // [64]
    float* __restrict__ out, int n)
{
    extern __shared__ float smem[];
    float* As = smem;                 // [192][66]
    float* Bs = smem + KDIM * SA;     // [192][64]

    int tid = threadIdx.x;
    int block_m = blockIdx.x * FM;

    // ---- W -> smem (12288 floats = 3072 float4) ----
    {
        const float4* src = (const float4*)Wg;
        float4* dst = (float4*)Bs;
        #pragma unroll
        for (int i = 0; i < 12; i++) dst[tid + 256 * i] = src[tid + 256 * i];
    }

    // ---- Phase 1: aggregation into As ----
    {
        int hw = tid >> 4;            // half-warp id 0..15
        int lane = tid & 15;
        #pragma unroll
        for (int it = 0; it < 4; it++) {
            int m = hw * 4 + it;
            int node = block_m + m;

            float4 sm4 = make_float4(0.f, 0.f, 0.f, 0.f);
            float4 mx4 = make_float4(-INFINITY, -INFINITY, -INFINITY, -INFINITY);
            float4 mn4 = make_float4( INFINITY,  INFINITY,  INFINITY,  INFINITY);

            if (node < n) {
                int s = g_start[node];
                int e = g_start[node + 1];
                int j = s;
                for (; j + 4 <= e; j += 4) {
                    int c0 = __ldg(&g_adj[j]);
                    int c1 = __ldg(&g_adj[j + 1]);
                    int c2 = __ldg(&g_adj[j + 2]);
                    int c3 = __ldg(&g_adj[j + 3]);
                    float4 f0 = *(const float4*)&feat[(size_t)c0 * D + 4 * lane];
                    float4 f1 = *(const float4*)&feat[(size_t)c1 * D + 4 * lane];
                    float4 f2 = *(const float4*)&feat[(size_t)c2 * D + 4 * lane];
                    float4 f3 = *(const float4*)&feat[(size_t)c3 * D + 4 * lane];
                    facc4(sm4, mx4, mn4, f0);
                    facc4(sm4, mx4, mn4, f1);
                    facc4(sm4, mx4, mn4, f2);
                    facc4(sm4, mx4, mn4, f3);
                }
                for (; j < e; j++) {
                    int c0 = __ldg(&g_adj[j]);
                    float4 f0 = *(const float4*)&feat[(size_t)c0 * D + 4 * lane];
                    facc4(sm4, mx4, mn4, f0);
                }
                if (e == s) {
                    mx4 = make_float4(0.f, 0.f, 0.f, 0.f);
                    mn4 = make_float4(0.f, 0.f, 0.f, 0.f);
                }
            } else {
                mx4 = make_float4(0.f, 0.f, 0.f, 0.f);
                mn4 = make_float4(0.f, 0.f, 0.f, 0.f);
            }

            int k0 = 4 * lane;
            As[(k0 + 0) * SA + m] = sm4.x;
            As[(k0 + 1) * SA + m] = sm4.y;
            As[(k0 + 2) * SA + m] = sm4.z;
            As[(k0 + 3) * SA + m] = sm4.w;
            As[(64 + k0 + 0) * SA + m] = mx4.x;
            As[(64 + k0 + 1) * SA + m] = mx4.y;
            As[(64 + k0 + 2) * SA + m] = mx4.z;
            As[(64 + k0 + 3) * SA + m] = mx4.w;
            As[(128 + k0 + 0) * SA + m] = mn4.x;
            As[(128 + k0 + 1) * SA + m] = mn4.y;
            As[(128 + k0 + 2) * SA + m] = mn4.z;
            As[(128 + k0 + 3) * SA + m] = mn4.w;
        }
    }
    __syncthreads();

    // ---- Phase 2: GEMM 64x64x192 with FFMA2 ----
    {
        int tx = tid & 15;            // 4 output cols
        int ty = tid >> 4;            // 4 output rows (2 row-pairs)

        u64 acc[2][4];
        #pragma unroll
        for (int i = 0; i < 2; i++)
            #pragma unroll
            for (int j = 0; j < 4; j++) acc[i][j] = 0ull;

        #pragma unroll 4
        for (int k = 0; k < KDIM; k++) {
            u64 ra0 = *(const u64*)&As[k * SA + ty * 4];      // broadcast LDS.64
            u64 ra1 = *(const u64*)&As[k * SA + ty * 4 + 2];
            float4 rbv = *(const float4*)&Bs[k * OUTC + tx * 4];
            u64 rb0 = pack2(rbv.x, rbv.x);
            u64 rb1 = pack2(rbv.y, rbv.y);
            u64 rb2 = pack2(rbv.z, rbv.z);
            u64 rb3 = pack2(rbv.w, rbv.w);
            ffma2(acc[0][0], ra0, rb0);
            ffma2(acc[0][1], ra0, rb1);
            ffma2(acc[0][2], ra0, rb2);
            ffma2(acc[0][3], ra0, rb3);
            ffma2(acc[1][0], ra1, rb0);
            ffma2(acc[1][1], ra1, rb1);
            ffma2(acc[1][2], ra1, rb2);
            ffma2(acc[1][3], ra1, rb3);
        }

        float4 bv = *(const float4*)&bg[tx * 4];
        #pragma unroll
        for (int i = 0; i < 2; i++) {
            float2 c0 = unpack2(acc[i][0]);
            float2 c1 = unpack2(acc[i][1]);
            float2 c2 = unpack2(acc[i][2]);
            float2 c3 = unpack2(acc[i][3]);
            int gm0 = block_m + ty * 4 + 2 * i;
            if (gm0 < n) {
                float4 o;
                o.x = tanhf(c0.x + bv.x); o.y = tanhf(c1.x + bv.y);
                o.z = tanhf(c2.x + bv.z); o.w = tanhf(c3.x + bv.w);
                *(float4*)&out[(size_t)gm0 * OUTC + tx * 4] = o;
            }
            if (gm0 + 1 < n) {
                float4 o;
                o.x = tanhf(c0.y + bv.x); o.y = tanhf(c1.y + bv.y);
                o.z = tanhf(c2.y + bv.z); o.w = tanhf(c3.y + bv.w);
                *(float4*)&out[(size_t)(gm0 + 1) * OUTC + tx * 4] = o;
            }
        }
    }
}

// ---------------- launch ----------------

extern "C" void kernel_launch(void* const* d_in, const int* in_sizes, int n_in,
                              void* d_out, int out_size) {
    const int*   row  = (const int*)d_in[0];
    const int*   col  = (const int*)d_in[1];
    const float* feat = (const float*)d_in[2];
    const float* W    = (const float*)d_in[3];
    const float* b    = (const float*)d_in[4];
    float* out = (float*)d_out;

    int E = in_sizes[0];
    int N = in_sizes[2] / D;
    int nb = (N + SCAN_B - 1) / SCAN_B;

    cudaFuncSetAttribute(fused_kernel,
                         cudaFuncAttributeMaxDynamicSharedMemorySize, SMEM_BYTES);

    zero_cnt_kernel<<<(N + 255) / 256, 256>>>(N);
    hist_kernel<<<(E + 255) / 256, 256>>>(row, E);
    scan_partial_kernel<<<nb, SCAN_B>>>(N);
    scan_bsums_kernel<<<1, 256>>>(nb);
    scan_add_kernel<<<nb, SCAN_B>>>(N);
    scatter_kernel<<<(E + 255) / 256, 256>>>(row, col, E);
    fused_kernel<<<(N + FM - 1) / FM, 256, SMEM_BYTES>>>(feat, W, b, out, N);
}

// round 8
// speedup vs baseline: 1.1921x; 1.1921x over previous
#include <cuda_runtime.h>
#include <math.h>

#define NMAX 100000
#define EMAX 1600000
#define D 64
#define KDIM 192
#define OUTC 64

typedef unsigned long long u64;

// ---- scratch ----
__device__ int   g_cnt[NMAX];
__device__ int   g_start[NMAX + 1];
__device__ int   g_cursor[NMAX];
__device__ int   g_adj[EMAX];
__device__ int   g_bsum[260];
__device__ float g_comb[(size_t)NMAX * KDIM];   // [N, 192] sum|max|min

// ---------------- CSR build ----------------

__global__ void zero_cnt_kernel(int n) {
    int i = blockIdx.x * blockDim.x + threadIdx.x;
    if (i < n) g_cnt[i] = 0;
}

// MLP=4 histogram: contiguous int4 load, 4 independent atomics in flight
__global__ __launch_bounds__(256) void hist_kernel(const int* __restrict__ row, int E) {
    int i4 = (blockIdx.x * blockDim.x + threadIdx.x) * 4;
    if (i4 + 3 < E) {
        int4 r = *(const int4*)&row[i4];
        atomicAdd(&g_cnt[r.x], 1);
        atomicAdd(&g_cnt[r.y], 1);
        atomicAdd(&g_cnt[r.z], 1);
        atomicAdd(&g_cnt[r.w], 1);
    } else {
        for (int i = i4; i < E; i++) atomicAdd(&g_cnt[row[i]], 1);
    }
}

#define SCAN_B 512

__global__ __launch_bounds__(SCAN_B) void scan_partial_kernel(int n) {
    __shared__ int ws[16];
    int blk = blockIdx.x, tid = threadIdx.x;
    int i = blk * SCAN_B + tid;
    int v = (i < n) ? g_cnt[i] : 0;
    int lane = tid & 31, wid = tid >> 5;
    int x = v;
    #pragma unroll
    for (int o = 1; o < 32; o <<= 1) {
        int y = __shfl_up_sync(0xffffffffu, x, o);
        if (lane >= o) x += y;
    }
    if (lane == 31) ws[wid] = x;
    __syncthreads();
    if (wid == 0 && lane < 16) {
        int w = ws[lane];
        #pragma unroll
        for (int o = 1; o < 16; o <<= 1) {
            int y = __shfl_up_sync(0x0000ffffu, w, o);
            if (lane >= o) w += y;
        }
        ws[lane] = w;
    }
    __syncthreads();
    int incl = x + (wid > 0 ? ws[wid - 1] : 0);
    if (i < n) g_start[i] = incl - v;          // block-local exclusive
    if (tid == SCAN_B - 1) g_bsum[blk] = incl; // block total
}

// scan_add with inlined block-offset reduction over g_bsum[0..bid)
__global__ __launch_bounds__(SCAN_B) void scan_add_kernel(int n, int nb) {
    __shared__ int ws[16];
    int bid = blockIdx.x, tid = threadIdx.x;
    int lane = tid & 31, wid = tid >> 5;

    int v = (tid < bid) ? g_bsum[tid] : 0;     // bid <= nb-1 < 512
    #pragma unroll
    for (int o = 16; o > 0; o >>= 1) v += __shfl_down_sync(0xffffffffu, v, o);
    if (lane == 0) ws[wid] = v;
    __syncthreads();
    if (wid == 0) {
        int w = (lane < 16) ? ws[lane] : 0;
        #pragma unroll
        for (int o = 8; o > 0; o >>= 1) w += __shfl_down_sync(0xffffffffu, w, o);
        if (lane == 0) ws[0] = w;
    }
    __syncthreads();
    int off = ws[0];

    int i = bid * SCAN_B + tid;
    if (i < n) {
        int s = g_start[i] + off;
        g_start[i] = s;
        g_cursor[i] = s;
    }
    if (tid == 0 && bid == nb - 1) g_start[n] = off + g_bsum[bid];
}

// MLP=4 scatter: contiguous int4 loads, 4 independent atomics, 4 stores
__global__ __launch_bounds__(256) void scatter_kernel(const int* __restrict__ row,
                                                      const int* __restrict__ col, int E) {
    int i4 = (blockIdx.x * blockDim.x + threadIdx.x) * 4;
    if (i4 + 3 < E) {
        int4 r = *(const int4*)&row[i4];
        int4 c = *(const int4*)&col[i4];
        int p0 = atomicAdd(&g_cursor[r.x], 1);
        int p1 = atomicAdd(&g_cursor[r.y], 1);
        int p2 = atomicAdd(&g_cursor[r.z], 1);
        int p3 = atomicAdd(&g_cursor[r.w], 1);
        g_adj[p0] = c.x;
        g_adj[p1] = c.y;
        g_adj[p2] = c.z;
        g_adj[p3] = c.w;
    } else {
        for (int i = i4; i < E; i++) {
            int p = atomicAdd(&g_cursor[row[i]], 1);
            g_adj[p] = col[i];
        }
    }
}

// ---------------- aggregation: half-warp per node, broadcast indices ----------------

__device__ __forceinline__ void acc4(float4& sm, float4& mx, float4& mn, float4 f) {
    sm.x += f.x;  sm.y += f.y;  sm.z += f.z;  sm.w += f.w;
    mx.x = fmaxf(mx.x, f.x);  mx.y = fmaxf(mx.y, f.y);
    mx.z = fmaxf(mx.z, f.z);  mx.w = fmaxf(mx.w, f.w);
    mn.x = fminf(mn.x, f.x);  mn.y = fminf(mn.y, f.y);
    mn.z = fminf(mn.z, f.z);  mn.w = fminf(mn.w, f.w);
}

__global__ __launch_bounds__(256) void aggregate_kernel(const float* __restrict__ feat, int n) {
    int gt   = blockIdx.x * blockDim.x + threadIdx.x;
    int node = gt >> 4;
    int lane = gt & 15;
    if (node >= n) return;

    int s = g_start[node];
    int e = g_start[node + 1];

    float4 sm = make_float4(0.f, 0.f, 0.f, 0.f);
    float4 mx = make_float4(-INFINITY, -INFINITY, -INFINITY, -INFINITY);
    float4 mn = make_float4( INFINITY,  INFINITY,  INFINITY,  INFINITY);

    int j = s;
    for (; j + 4 <= e; j += 4) {
        int c0 = __ldg(&g_adj[j]);
        int c1 = __ldg(&g_adj[j + 1]);
        int c2 = __ldg(&g_adj[j + 2]);
        int c3 = __ldg(&g_adj[j + 3]);
        float4 f0 = *(const float4*)&feat[(size_t)c0 * D + 4 * lane];
        float4 f1 = *(const float4*)&feat[(size_t)c1 * D + 4 * lane];
        float4 f2 = *(const float4*)&feat[(size_t)c2 * D + 4 * lane];
        float4 f3 = *(const float4*)&feat[(size_t)c3 * D + 4 * lane];
        acc4(sm, mx, mn, f0);
        acc4(sm, mx, mn, f1);
        acc4(sm, mx, mn, f2);
        acc4(sm, mx, mn, f3);
    }
    for (; j < e; j++) {
        int c0 = __ldg(&g_adj[j]);
        float4 f0 = *(const float4*)&feat[(size_t)c0 * D + 4 * lane];
        acc4(sm, mx, mn, f0);
    }
    if (e == s) {
        mx = make_float4(0.f, 0.f, 0.f, 0.f);
        mn = make_float4(0.f, 0.f, 0.f, 0.f);
    }

    float* cb = &g_comb[(size_t)node * KDIM];
    *(float4*)&cb[        4 * lane] = sm;
    *(float4*)&cb[ D  +   4 * lane] = mx;
    *(float4*)&cb[2*D +   4 * lane] = mn;
}

// ---------------- MLP GEMM with packed f32x2 FMA ----------------

__device__ __forceinline__ u64 pack2(float lo, float hi) {
    u64 r; asm("mov.b64 %0, {%1, %2};" : "=l"(r) : "f"(lo), "f"(hi)); return r;
}
__device__ __forceinline__ void ffma2(u64& d, u64 a, u64 b) {
    asm("fma.rn.f32x2 %0, %1, %2, %0;" : "+l"(d) : "l"(a), "l"(b));
}
__device__ __forceinline__ float2 unpack2(u64 v) {
    float2 f; asm("mov.b64 {%0, %1}, %2;" : "=f"(f.x), "=f"(f.y) : "l"(v)); return f;
}

#define BM 128
#define BK 16
#define BN 64

__global__ __launch_bounds__(256) void mlp_gemm_kernel(
    const float* __restrict__ Wg,     // [192,64]
    const float* __restrict__ bg,     // [64]
    float* __restrict__ out, int n)
{
    __shared__ float As[BK][BM];
    __shared__ float Bs[BK][BN];

    const float* __restrict__ A = g_comb;

    int tid = threadIdx.x;
    int block_m = blockIdx.x * BM;
    int tx = tid & 15;                // 4 output cols
    int ty = tid >> 4;                // 8 output rows (4 row-pairs)

    int a_row  = tid >> 2;
    int a_col4 = (tid & 3) * 4;
    int b_row  = tid >> 4;
    int b_col4 = (tid & 15) * 4;

    u64 acc[4][4];
    #pragma unroll
    for (int i = 0; i < 4; i++)
        #pragma unroll
        for (int j = 0; j < 4; j++) acc[i][j] = 0ull;

    for (int k0 = 0; k0 < KDIM; k0 += BK) {
        #pragma unroll
        for (int r = 0; r < 2; r++) {
            int m  = a_row + r * 64;
            int gm = block_m + m;
            float4 v = make_float4(0.f, 0.f, 0.f, 0.f);
            if (gm < n) v = *(const float4*)&A[(size_t)gm * KDIM + k0 + a_col4];
            As[a_col4 + 0][m] = v.x;
            As[a_col4 + 1][m] = v.y;
            As[a_col4 + 2][m] = v.z;
            As[a_col4 + 3][m] = v.w;
        }
        *(float4*)&Bs[b_row][b_col4] =
            *(const float4*)&Wg[(size_t)(k0 + b_row) * BN + b_col4];
        __syncthreads();

        #pragma unroll
        for (int k = 0; k < BK; k++) {
            u64 ra[4];
            #pragma unroll
            for (int i = 0; i < 4; i++)
                ra[i] = *(const u64*)&As[k][ty * 8 + 2 * i];   // LDS.64, row pair
            float4 rbv = *(const float4*)&Bs[k][tx * 4];
            u64 rb[4];
            rb[0] = pack2(rbv.x, rbv.x);
            rb[1] = pack2(rbv.y, rbv.y);
            rb[2] = pack2(rbv.z, rbv.z);
            rb[3] = pack2(rbv.w, rbv.w);
            #pragma unroll
            for (int i = 0; i < 4; i++)
                #pragma unroll
                for (int j = 0; j < 4; j++)
                    ffma2(acc[i][j], ra[i], rb[j]);
        }
        __syncthreads();
    }

    float4 bv = *(const float4*)&bg[tx * 4];
    #pragma unroll
    for (int i = 0; i < 4; i++) {
        float2 c0 = unpack2(acc[i][0]);
        float2 c1 = unpack2(acc[i][1]);
        float2 c2 = unpack2(acc[i][2]);
        float2 c3 = unpack2(acc[i][3]);
        int gm0 = block_m + ty * 8 + 2 * i;
        if (gm0 < n) {
            float4 o;
            o.x = tanhf(c0.x + bv.x); o.y = tanhf(c1.x + bv.y);
            o.z = tanhf(c2.x + bv.z); o.w = tanhf(c3.x + bv.w);
            *(float4*)&out[(size_t)gm0 * OUTC + tx * 4] = o;
        }
        if (gm0 + 1 < n) {
            float4 o;
            o.x = tanhf(c0.y + bv.x); o.y = tanhf(c1.y + bv.y);
            o.z = tanhf(c2.y + bv.z); o.w = tanhf(c3.y + bv.w);
            *(float4*)&out[(size_t)(gm0 + 1) * OUTC + tx * 4] = o;
        }
    }
}

// ---------------- launch ----------------

extern "C" void kernel_launch(void* const* d_in, const int* in_sizes, int n_in,
                              void* d_out, int out_size) {
    const int*   row  = (const int*)d_in[0];
    const int*   col  = (const int*)d_in[1];
    const float* feat = (const float*)d_in[2];
    const float* W    = (const float*)d_in[3];
    const float* b    = (const float*)d_in[4];
    float* out = (float*)d_out;

    int E = in_sizes[0];
    int N = in_sizes[2] / D;
    int nb = (N + SCAN_B - 1) / SCAN_B;
    int e4blocks = ((E + 3) / 4 + 255) / 256;

    zero_cnt_kernel<<<(N + 255) / 256, 256>>>(N);
    hist_kernel<<<e4blocks, 256>>>(row, E);
    scan_partial_kernel<<<nb, SCAN_B>>>(N);
    scan_add_kernel<<<nb, SCAN_B>>>(N, nb);
    scatter_kernel<<<e4blocks, 256>>>(row, col, E);
    aggregate_kernel<<<(N * 16 + 255) / 256, 256>>>(feat, N);
    mlp_gemm_kernel<<<(N + BM - 1) / BM, 256>>>(W, b, out, N);
}

// round 9
// speedup vs baseline: 1.2500x; 1.0486x over previous
#include <cuda_runtime.h>
#include <cuda_fp16.h>
#include <math.h>
#include <cstdint>

#define NMAX 100000
#define EMAX 1600000
#define D 64
#define KDIM 192
#define OUTC 64

typedef unsigned long long u64;

// ---- scratch ----
__device__ int   g_cnt[NMAX];          // zero-init; self-cleaned by scan_partial
__device__ int   g_start[NMAX + 1];
__device__ int   g_cursor[NMAX];
__device__ int   g_adj[EMAX];
__device__ int   g_bsum[260];
__device__ uint2 g_feat16[(size_t)NMAX * 16];   // [N, 64] fp16, 4 dims per uint2
__device__ float g_comb[(size_t)NMAX * KDIM];   // [N, 192] sum|max|min

// ---------------- feature fp32 -> fp16 conversion ----------------

__global__ __launch_bounds__(256) void featcvt_kernel(const float* __restrict__ feat, int total4) {
    int i = blockIdx.x * blockDim.x + threadIdx.x;   // over N*D/4
    if (i < total4) {
        float4 v = *(const float4*)&feat[(size_t)i * 4];
        __half2 h0 = __floats2half2_rn(v.x, v.y);
        __half2 h1 = __floats2half2_rn(v.z, v.w);
        uint2 u;
        u.x = *(uint32_t*)&h0;
        u.y = *(uint32_t*)&h1;
        g_feat16[i] = u;
    }
}

// ---------------- CSR build ----------------

__global__ void hist_kernel(const int* __restrict__ row, int E) {
    int i = blockIdx.x * blockDim.x + threadIdx.x;
    if (i < E) atomicAdd(&g_cnt[row[i]], 1);
}

#define SCAN_B 512

__global__ __launch_bounds__(SCAN_B) void scan_partial_kernel(int n) {
    __shared__ int ws[16];
    int blk = blockIdx.x, tid = threadIdx.x;
    int i = blk * SCAN_B + tid;
    int v = (i < n) ? g_cnt[i] : 0;
    if (i < n) g_cnt[i] = 0;                   // self-clean for next call
    int lane = tid & 31, wid = tid >> 5;
    int x = v;
    #pragma unroll
    for (int o = 1; o < 32; o <<= 1) {
        int y = __shfl_up_sync(0xffffffffu, x, o);
        if (lane >= o) x += y;
    }
    if (lane == 31) ws[wid] = x;
    __syncthreads();
    if (wid == 0 && lane < 16) {
        int w = ws[lane];
        #pragma unroll
        for (int o = 1; o < 16; o <<= 1) {
            int y = __shfl_up_sync(0x0000ffffu, w, o);
            if (lane >= o) w += y;
        }
        ws[lane] = w;
    }
    __syncthreads();
    int incl = x + (wid > 0 ? ws[wid - 1] : 0);
    if (i < n) g_start[i] = incl - v;          // block-local exclusive
    if (tid == SCAN_B - 1) g_bsum[blk] = incl; // block total
}

// scan_add with inlined block-offset reduction over g_bsum[0..bid)
__global__ __launch_bounds__(SCAN_B) void scan_add_kernel(int n, int nb) {
    __shared__ int ws[16];
    int bid = blockIdx.x, tid = threadIdx.x;
    int lane = tid & 31, wid = tid >> 5;

    int v = (tid < bid) ? g_bsum[tid] : 0;
    #pragma unroll
    for (int o = 16; o > 0; o >>= 1) v += __shfl_down_sync(0xffffffffu, v, o);
    if (lane == 0) ws[wid] = v;
    __syncthreads();
    if (wid == 0) {
        int w = (lane < 16) ? ws[lane] : 0;
        #pragma unroll
        for (int o = 8; o > 0; o >>= 1) w += __shfl_down_sync(0xffffffffu, w, o);
        if (lane == 0) ws[0] = w;
    }
    __syncthreads();
    int off = ws[0];

    int i = bid * SCAN_B + tid;
    if (i < n) {
        int s = g_start[i] + off;
        g_start[i] = s;
        g_cursor[i] = s;
    }
    if (tid == 0 && bid == nb - 1) g_start[n] = off + g_bsum[bid];
}

__global__ void scatter_kernel(const int* __restrict__ row,
                               const int* __restrict__ col, int E) {
    int i = blockIdx.x * blockDim.x + threadIdx.x;
    if (i < E) {
        int p = atomicAdd(&g_cursor[row[i]], 1);
        g_adj[p] = col[i];
    }
}

// ---------------- aggregation: half-warp per node, fp16 gathers ----------------
// 16 lanes x 4 dims (uint2 = 2 half2) = 64 dims; 128B per edge per half-warp.
// max/min in half2 SIMD (monotonic => exact picks), sum accumulated in fp32.

__device__ __forceinline__ void acc16(float4& sm, __half2& mxa, __half2& mxb,
                                      __half2& mna, __half2& mnb, uint2 u) {
    __half2 h0 = *(__half2*)&u.x;
    __half2 h1 = *(__half2*)&u.y;
    mxa = __hmax2(mxa, h0);  mxb = __hmax2(mxb, h1);
    mna = __hmin2(mna, h0);  mnb = __hmin2(mnb, h1);
    float2 f0 = __half22float2(h0);
    float2 f1 = __half22float2(h1);
    sm.x += f0.x;  sm.y += f0.y;  sm.z += f1.x;  sm.w += f1.y;
}

__global__ __launch_bounds__(256) void aggregate_kernel(int n) {
    int gt   = blockIdx.x * blockDim.x + threadIdx.x;
    int node = gt >> 4;
    int lane = gt & 15;
    if (node >= n) return;

    int s = g_start[node];
    int e = g_start[node + 1];

    float4 sm = make_float4(0.f, 0.f, 0.f, 0.f);
    __half2 ninf2 = __float2half2_rn(-INFINITY);
    __half2 pinf2 = __float2half2_rn( INFINITY);
    __half2 mxa = ninf2, mxb = ninf2;
    __half2 mna = pinf2, mnb = pinf2;

    int j = s;
    for (; j + 4 <= e; j += 4) {
        int c0 = __ldg(&g_adj[j]);
        int c1 = __ldg(&g_adj[j + 1]);
        int c2 = __ldg(&g_adj[j + 2]);
        int c3 = __ldg(&g_adj[j + 3]);
        uint2 u0 = g_feat16[(size_t)c0 * 16 + lane];
        uint2 u1 = g_feat16[(size_t)c1 * 16 + lane];
        uint2 u2 = g_feat16[(size_t)c2 * 16 + lane];
        uint2 u3 = g_feat16[(size_t)c3 * 16 + lane];
        acc16(sm, mxa, mxb, mna, mnb, u0);
        acc16(sm, mxa, mxb, mna, mnb, u1);
        acc16(sm, mxa, mxb, mna, mnb, u2);
        acc16(sm, mxa, mxb, mna, mnb, u3);
    }
    for (; j < e; j++) {
        int c0 = __ldg(&g_adj[j]);
        uint2 u0 = g_feat16[(size_t)c0 * 16 + lane];
        acc16(sm, mxa, mxb, mna, mnb, u0);
    }

    float4 mx, mn;
    {
        float2 a = __half22float2(mxa), bq = __half22float2(mxb);
        mx = make_float4(a.x, a.y, bq.x, bq.y);
        float2 c = __half22float2(mna), dq = __half22float2(mnb);
        mn = make_float4(c.x, c.y, dq.x, dq.y);
    }
    if (e == s) {
        mx = make_float4(0.f, 0.f, 0.f, 0.f);
        mn = make_float4(0.f, 0.f, 0.f, 0.f);
    }

    float* cb = &g_comb[(size_t)node * KDIM];
    *(float4*)&cb[        4 * lane] = sm;
    *(float4*)&cb[ D  +   4 * lane] = mx;
    *(float4*)&cb[2*D +   4 * lane] = mn;
}

// ---------------- MLP GEMM with packed f32x2 FMA ----------------

__device__ __forceinline__ u64 pack2(float lo, float hi) {
    u64 r; asm("mov.b64 %0, {%1, %2};" : "=l"(r) : "f"(lo), "f"(hi)); return r;
}
__device__ __forceinline__ void ffma2(u64& d, u64 a, u64 b) {
    asm("fma.rn.f32x2 %0, %1, %2, %0;" : "+l"(d) : "l"(a), "l"(b));
}
__device__ __forceinline__ float2 unpack2(u64 v) {
    float2 f; asm("mov.b64 {%0, %1}, %2;" : "=f"(f.x), "=f"(f.y) : "l"(v)); return f;
}

#define BM 128
#define BK 16
#define BN 64

__global__ __launch_bounds__(256) void mlp_gemm_kernel(
    const float* __restrict__ Wg,     // [192,64]
    const float* __restrict__ bg,     // [64]
    float* __restrict__ out, int n)
{
    __shared__ float As[BK][BM];
    __shared__ float Bs[BK][BN];

    const float* __restrict__ A = g_comb;

    int tid = threadIdx.x;
    int block_m = blockIdx.x * BM;
    int tx = tid & 15;
    int ty = tid >> 4;

    int a_row  = tid >> 2;
    int a_col4 = (tid & 3) * 4;
    int b_row  = tid >> 4;
    int b_col4 = (tid & 15) * 4;

    u64 acc[4][4];
    #pragma unroll
    for (int i = 0; i < 4; i++)
        #pragma unroll
        for (int j = 0; j < 4; j++) acc[i][j] = 0ull;

    for (int k0 = 0; k0 < KDIM; k0 += BK) {
        #pragma unroll
        for (int r = 0; r < 2; r++) {
            int m  = a_row + r * 64;
            int gm = block_m + m;
            float4 v = make_float4(0.f, 0.f, 0.f, 0.f);
            if (gm < n) v = *(const float4*)&A[(size_t)gm * KDIM + k0 + a_col4];
            As[a_col4 + 0][m] = v.x;
            As[a_col4 + 1][m] = v.y;
            As[a_col4 + 2][m] = v.z;
            As[a_col4 + 3][m] = v.w;
        }
        *(float4*)&Bs[b_row][b_col4] =
            *(const float4*)&Wg[(size_t)(k0 + b_row) * BN + b_col4];
        __syncthreads();

        #pragma unroll
        for (int k = 0; k < BK; k++) {
            u64 ra[4];
            #pragma unroll
            for (int i = 0; i < 4; i++)
                ra[i] = *(const u64*)&As[k][ty * 8 + 2 * i];
            float4 rbv = *(const float4*)&Bs[k][tx * 4];
            u64 rb[4];
            rb[0] = pack2(rbv.x, rbv.x);
            rb[1] = pack2(rbv.y, rbv.y);
            rb[2] = pack2(rbv.z, rbv.z);
            rb[3] = pack2(rbv.w, rbv.w);
            #pragma unroll
            for (int i = 0; i < 4; i++)
                #pragma unroll
                for (int j = 0; j < 4; j++)
                    ffma2(acc[i][j], ra[i], rb[j]);
        }
        __syncthreads();
    }

    float4 bv = *(const float4*)&bg[tx * 4];
    #pragma unroll
    for (int i = 0; i < 4; i++) {
        float2 c0 = unpack2(acc[i][0]);
        float2 c1 = unpack2(acc[i][1]);
        float2 c2 = unpack2(acc[i][2]);
        float2 c3 = unpack2(acc[i][3]);
        int gm0 = block_m + ty * 8 + 2 * i;
        if (gm0 < n) {
            float4 o;
            o.x = tanhf(c0.x + bv.x); o.y = tanhf(c1.x + bv.y);
            o.z = tanhf(c2.x + bv.z); o.w = tanhf(c3.x + bv.w);
            *(float4*)&out[(size_t)gm0 * OUTC + tx * 4] = o;
        }
        if (gm0 + 1 < n) {
            float4 o;
            o.x = tanhf(c0.y + bv.x); o.y = tanhf(c1.y + bv.y);
            o.z = tanhf(c2.y + bv.z); o.w = tanhf(c3.y + bv.w);
            *(float4*)&out[(size_t)(gm0 + 1) * OUTC + tx * 4] = o;
        }
    }
}

// ---------------- launch ----------------

extern "C" void kernel_launch(void* const* d_in, const int* in_sizes, int n_in,
                              void* d_out, int out_size) {
    const int*   row  = (const int*)d_in[0];
    const int*   col  = (const int*)d_in[1];
    const float* feat = (const float*)d_in[2];
    const float* W    = (const float*)d_in[3];
    const float* b    = (const float*)d_in[4];
    float* out = (float*)d_out;

    int E = in_sizes[0];
    int N = in_sizes[2] / D;
    int nb = (N + SCAN_B - 1) / SCAN_B;
    int total4 = N * D / 4;

    featcvt_kernel<<<(total4 + 255) / 256, 256>>>(feat, total4);
    hist_kernel<<<(E + 255) / 256, 256>>>(row, E);
    scan_partial_kernel<<<nb, SCAN_B>>>(N);
    scan_add_kernel<<<nb, SCAN_B>>>(N, nb);
    scatter_kernel<<<(E + 255) / 256, 256>>>(row, col, E);
    aggregate_kernel<<<(N * 16 + 255) / 256, 256>>>(N);
    mlp_gemm_kernel<<<(N + BM - 1) / BM, 256>>>(W, b, out, N);
}